// round 2
// baseline (speedup 1.0000x reference)
#include <cuda_runtime.h>

// ObservabilityWeightedMSE — fused single-pass weighted-MSE reduction.
// d_in[0]=predictions [500000,82] f32, d_in[1]=targets [500000,82] f32,
// d_in[2]=inputs [500000,400] f32. Output: scalar f32.

#define THRESH   1e-4f
#define NCOLS    82
#define ROW_IN   400
#define NBLOCKS  1184
#define NTHREADS 256

__device__ float g_part[NBLOCKS];

// spatial mask weight * dynamic cutoff weight for column c (0..81)
__device__ __forceinline__ float wfun(int c, int cutoff) {
    int col; bool five;
    if (c < 41) { col = c; five = ((c & 3) == 0); }
    else {
        int j = c - 41; col = j;
        five = ((j & 3) == 3) || (((j & 3) == 0) && (j != 40));
    }
    float w = five ? 5.0f : 1.0f;
    if (col >= cutoff) w *= 0.1f;
    return w;
}

__global__ void __launch_bounds__(NTHREADS)
wmse_kernel(const float* __restrict__ pred,
            const float* __restrict__ targ,
            const float* __restrict__ inp,
            int B)
{
    const int lane  = threadIdx.x & 31;
    const int warp  = threadIdx.x >> 5;
    const int gwarp = blockIdx.x * (NTHREADS / 32) + warp;
    const int nwarp = gridDim.x * (NTHREADS / 32);

    // static per-lane geometry
    const int  n0 = lane / 5, p0 = lane % 5;           // inputs float4 #0 (idx = lane)
    const int  i1 = 32 + lane;
    const int  n1 = i1 / 5,  p1 = i1 % 5;              // inputs float4 #1 (idx = 32+lane)
    const bool has1  = (i1 < 50);                      // lanes 0..17
    const bool hasJ1 = (lane < 9);                     // float2 idx 32+lane < 41

    float acc = 0.0f;

    for (int r0 = gwarp; r0 < B; r0 += 2 * nwarp) {
        const int  r1    = r0 + nwarp;
        const bool hasR1 = (r1 < B);
        const int  r1s   = hasR1 ? r1 : r0;            // safe pointer for tail

        const float* pinA = inp  + (size_t)r0  * ROW_IN;
        const float* pinB = inp  + (size_t)r1s * ROW_IN;
        const float* ppA  = pred + (size_t)r0  * NCOLS;
        const float* ptA  = targ + (size_t)r0  * NCOLS;
        const float* ppB  = pred + (size_t)r1s * NCOLS;
        const float* ptB  = targ + (size_t)r1s * NCOLS;

        // ---------- front-batched loads: all 12 LDGs before any sync ----------
        float4 a0 = *(const float4*)(pinA + n0 * 40 + p0 * 4);
        float4 b0 = *(const float4*)(pinB + n0 * 40 + p0 * 4);
        float4 a1 = make_float4(0.f, 0.f, 0.f, 0.f);
        float4 b1 = make_float4(0.f, 0.f, 0.f, 0.f);
        if (has1) {
            a1 = *(const float4*)(pinA + n1 * 40 + p1 * 4);
            b1 = *(const float4*)(pinB + n1 * 40 + p1 * 4);
        }

        float2 pA0 = ((const float2*)ppA)[lane];
        float2 tA0 = ((const float2*)ptA)[lane];
        float2 pB0 = ((const float2*)ppB)[lane];
        float2 tB0 = ((const float2*)ptB)[lane];
        float2 pA1 = make_float2(0.f, 0.f), tA1 = make_float2(0.f, 0.f);
        float2 pB1 = make_float2(0.f, 0.f), tB1 = make_float2(0.f, 0.f);
        if (hasJ1) {
            pA1 = ((const float2*)ppA)[32 + lane];
            tA1 = ((const float2*)ptA)[32 + lane];
            pB1 = ((const float2*)ppB)[32 + lane];
            tB1 = ((const float2*)ptB)[32 + lane];
        }

        // ---------- node-below bits -> stage cutoffs ----------
        unsigned okA = 0, okB = 0;
        if (a0.x >= THRESH || a0.y >= THRESH || a0.z >= THRESH || a0.w >= THRESH)
            okA = 1u << n0;
        if (has1 && (a1.x >= THRESH || a1.y >= THRESH || a1.z >= THRESH || a1.w >= THRESH))
            okA |= 1u << n1;
        if (b0.x >= THRESH || b0.y >= THRESH || b0.z >= THRESH || b0.w >= THRESH)
            okB = 1u << n0;
        if (has1 && (b1.x >= THRESH || b1.y >= THRESH || b1.z >= THRESH || b1.w >= THRESH))
            okB |= 1u << n1;

        unsigned belowA = (~__reduce_or_sync(0xffffffffu, okA)) & 0x3FFu;
        unsigned belowB = (~__reduce_or_sync(0xffffffffu, okB)) & 0x3FFu;
        const int cutA = belowA ? (__ffs(belowA) << 2) : 1000;
        const int cutB = belowB ? (__ffs(belowB) << 2) : 1000;

        // ---------- weighted MSE ----------
        {
            int c = 2 * lane;
            float d = pA0.x - tA0.x; acc = fmaf(d * d, wfun(c,     cutA), acc);
            d       = pA0.y - tA0.y; acc = fmaf(d * d, wfun(c + 1, cutA), acc);
            if (hasJ1) {
                int c2 = 64 + 2 * lane;
                d = pA1.x - tA1.x; acc = fmaf(d * d, wfun(c2,     cutA), acc);
                d = pA1.y - tA1.y; acc = fmaf(d * d, wfun(c2 + 1, cutA), acc);
            }
        }
        if (hasR1) {
            int c = 2 * lane;
            float d = pB0.x - tB0.x; acc = fmaf(d * d, wfun(c,     cutB), acc);
            d       = pB0.y - tB0.y; acc = fmaf(d * d, wfun(c + 1, cutB), acc);
            if (hasJ1) {
                int c2 = 64 + 2 * lane;
                d = pB1.x - tB1.x; acc = fmaf(d * d, wfun(c2,     cutB), acc);
                d = pB1.y - tB1.y; acc = fmaf(d * d, wfun(c2 + 1, cutB), acc);
            }
        }
    }

    // ---------- block reduction, one partial write per block ----------
    #pragma unroll
    for (int o = 16; o > 0; o >>= 1)
        acc += __shfl_down_sync(0xffffffffu, acc, o);

    __shared__ float smem[NTHREADS / 32];
    if (lane == 0) smem[warp] = acc;
    __syncthreads();
    if (warp == 0) {
        float v = (lane < (NTHREADS / 32)) ? smem[lane] : 0.0f;
        #pragma unroll
        for (int o = 4; o > 0; o >>= 1)
            v += __shfl_down_sync(0xffffffffu, v, o);
        if (lane == 0) g_part[blockIdx.x] = v;
    }
}

__global__ void __launch_bounds__(1024)
finalize_kernel(float* out, int nparts, double inv_total)
{
    __shared__ double s[32];
    double a = 0.0;
    for (int i = threadIdx.x; i < nparts; i += blockDim.x)
        a += (double)g_part[i];
    #pragma unroll
    for (int o = 16; o > 0; o >>= 1)
        a += __shfl_down_sync(0xffffffffu, a, o);
    int lane = threadIdx.x & 31, w = threadIdx.x >> 5;
    if (lane == 0) s[w] = a;
    __syncthreads();
    if (w == 0) {
        a = (lane < 32) ? s[lane] : 0.0;
        #pragma unroll
        for (int o = 16; o > 0; o >>= 1)
            a += __shfl_down_sync(0xffffffffu, a, o);
        if (lane == 0) out[0] = (float)(a * inv_total);
    }
}

extern "C" void kernel_launch(void* const* d_in, const int* in_sizes, int n_in,
                              void* d_out, int out_size)
{
    const float* pred = (const float*)d_in[0];
    const float* targ = (const float*)d_in[1];
    const float* inp  = (const float*)d_in[2];
    float* out = (float*)d_out;

    const int B = in_sizes[0] / NCOLS;   // 500000

    wmse_kernel<<<NBLOCKS, NTHREADS>>>(pred, targ, inp, B);
    finalize_kernel<<<1, 1024>>>(out, NBLOCKS, 1.0 / ((double)B * NCOLS));
}